// round 11
// baseline (speedup 1.0000x reference)
#include <cuda_runtime.h>
#include <cuda_fp16.h>
#include <cstdint>

#define Tn    512
#define Bn    4
#define En    1024
#define Hn    16
#define HDn   64
#define NBn   32
#define TGTn  1536
#define BHn   64
#define Mrows (TGTn*Bn)   /* 6144 */
#define LOG2E 1.442695041f

// -------- scratch (static device globals) --------
__device__ __half g_x_h[(size_t)Mrows*En],    g_x_l[(size_t)Mrows*En];
__device__ __half g_ipw_h[(size_t)3*En*En],   g_ipw_l[(size_t)3*En*En];
__device__ __half g_relw_h[(size_t)NBn*Hn*En],g_relw_l[(size_t)NBn*Hn*En];
__device__ __half g_outw_h[(size_t)En*En],    g_outw_l[(size_t)En*En];
__device__ __half g_ctx_h[(size_t)Mrows*En],  g_ctx_l[(size_t)Mrows*En];
__device__ __half g_q_h[(size_t)BHn*TGTn*HDn], g_q_l[(size_t)BHn*TGTn*HDn];
__device__ __half g_k_h[(size_t)BHn*TGTn*HDn], g_k_l[(size_t)BHn*TGTn*HDn];
__device__ __half g_v_h[(size_t)BHn*TGTn*HDn], g_v_l[(size_t)BHn*TGTn*HDn];
__device__ float  g_vals[(size_t)Bn*TGTn*Hn*NBn];   // [b][tg][h][nb], pre-scaled by LOG2E

// ============================ helpers ==================================
__device__ __forceinline__ uint32_t smem_u32(const void* p) {
    uint32_t a;
    asm("{ .reg .u64 t; cvta.to.shared.u64 t, %1; cvt.u32.u64 %0, t; }"
        : "=r"(a) : "l"(p));
    return a;
}
__device__ __forceinline__ void ldsm4(uint32_t* r, uint32_t addr) {
    asm volatile("ldmatrix.sync.aligned.m8n8.x4.shared.b16 {%0,%1,%2,%3}, [%4];"
                 : "=r"(r[0]), "=r"(r[1]), "=r"(r[2]), "=r"(r[3]) : "r"(addr));
}
__device__ __forceinline__ void ldsm4t(uint32_t* r, uint32_t addr) {
    asm volatile("ldmatrix.sync.aligned.m8n8.x4.trans.shared.b16 {%0,%1,%2,%3}, [%4];"
                 : "=r"(r[0]), "=r"(r[1]), "=r"(r[2]), "=r"(r[3]) : "r"(addr));
}
__device__ __forceinline__ void mma16816(float* c, const uint32_t* a, const uint32_t* b) {
    asm volatile(
        "mma.sync.aligned.m16n8k16.row.col.f32.f16.f16.f32 "
        "{%0,%1,%2,%3}, {%4,%5,%6,%7}, {%8,%9}, {%0,%1,%2,%3};"
        : "+f"(c[0]), "+f"(c[1]), "+f"(c[2]), "+f"(c[3])
        : "r"(a[0]), "r"(a[1]), "r"(a[2]), "r"(a[3]), "r"(b[0]), "r"(b[1]));
}
__device__ __forceinline__ void cp16(uint32_t dst, const void* src) {
    asm volatile("cp.async.cg.shared.global [%0], [%1], 16;"
                 :: "r"(dst), "l"(src) : "memory");
}
#define CP_COMMIT() asm volatile("cp.async.commit_group;" ::: "memory")
#define CP_WAIT(N)  asm volatile("cp.async.wait_group %0;" :: "n"(N) : "memory")

__device__ __forceinline__ void split2(float x, float y, uint32_t& hi, uint32_t& lo) {
    __half hx = __float2half_rn(x), hy = __float2half_rn(y);
    __half lx = __float2half_rn(x - __half2float(hx));
    __half ly = __float2half_rn(y - __half2float(hy));
    __half2 h = __halves2half2(hx, hy), l = __halves2half2(lx, ly);
    hi = *(uint32_t*)&h; lo = *(uint32_t*)&l;
}
__device__ __forceinline__ float2 h2sum(uint32_t h, uint32_t l) {
    float2 a = __half22float2(*(__half2*)&h);
    float2 b = __half22float2(*(__half2*)&l);
    return make_float2(a.x + b.x, a.y + b.y);
}
__device__ __forceinline__ float ex2(float x) {
    float r;
    asm("ex2.approx.ftz.f32 %0, %1;" : "=f"(r) : "f"(x));
    return r;
}

// ---------------------------------------------------------------------------
// Fused pre-convert: f32 -> fp16 hi/lo for all four operand tensors.
// ---------------------------------------------------------------------------
__global__ __launch_bounds__(256) void convert_all(
    const float* __restrict__ q, const float* __restrict__ w1,
    const float* __restrict__ w2, const float* __restrict__ w3)
{
    int bid = blockIdx.x;
    const float* src; __half *dh, *dl; int lb;
    if (bid < 6144)      { src = q;  dh = g_x_h;    dl = g_x_l;    lb = bid; }
    else if (bid < 9216) { src = w1; dh = g_ipw_h;  dl = g_ipw_l;  lb = bid - 6144; }
    else if (bid < 9728) { src = w2; dh = g_relw_h; dl = g_relw_l; lb = bid - 9216; }
    else                 { src = w3; dh = g_outw_h; dl = g_outw_l; lb = bid - 9728; }
    int i = (lb * 256 + threadIdx.x) * 4;
    float4 v = *(const float4*)(src + i);
    uint32_t h01, l01, h23, l23;
    split2(v.x, v.y, h01, l01);
    split2(v.z, v.w, h23, l23);
    *(uint2*)(dh + i) = make_uint2(h01, h23);
    *(uint2*)(dl + i) = make_uint2(l01, l23);
}

// ---------------------------------------------------------------------------
// HMMA GEMM (fp16 split 3-pass, cp.async 2-stage, single sync per chunk).
// BM templated: 128 (qkv) or 64 (out-proj, doubles grid for wave balance).
// MODE 0: A=g_ctx, B=g_outw -> C (fp32)
// MODE 1: A=g_x, B=[g_ipw | g_relw] (N=3584). Cols <3072 -> q/k/v scatter
//         (q scaled 0.125*LOG2E); cols >=3072 -> g_vals (scaled LOG2E).
// ---------------------------------------------------------------------------
#define RS 80
#define MATB (128*RS)
#define STAGEB (4*MATB)
#define SM_GEMM (2*STAGEB)

template<int MODE, int BM>
__global__ __launch_bounds__(256, 2) void hgemm2(
    const float* __restrict__ bias, const float* __restrict__ bias2,
    float* __restrict__ C, int M, int N, int K)
{
    constexpr int MT = BM / 32;          // 16-row m-subtiles per warp
    extern __shared__ __align__(16) char smem[];
    const __half* Ah = (MODE == 0) ? g_ctx_h : g_x_h;
    const __half* Al = (MODE == 0) ? g_ctx_l : g_x_l;

    int tid = threadIdx.x, lane = tid & 31, wid = tid >> 5;
    int wm = wid & 1, wn = wid >> 1;
    int m0 = blockIdx.y * BM, n0 = blockIdx.x * 128;
    uint32_t sbase = smem_u32(smem);

    const __half *Bh, *Bl; int nb0;
    if (MODE == 1 && n0 >= 3*En) { Bh = g_relw_h; Bl = g_relw_l; nb0 = n0 - 3*En; }
    else if (MODE == 1)          { Bh = g_ipw_h;  Bl = g_ipw_l;  nb0 = n0; }
    else                         { Bh = g_outw_h; Bl = g_outw_l; nb0 = n0; }

    int rowA = (lane & 7) + ((lane >> 3) & 1) * 8;
    int colA = ((lane >> 4) & 1) * 16;
    int rowB = (lane & 7) + ((lane >> 4) & 1) * 8;
    int colB = ((lane >> 3) & 1) * 16;
    uint32_t offAh = (uint32_t)((wm*(BM/2) + rowA) * RS + colA);
    uint32_t offAl = offAh + MATB;
    uint32_t offBh = (uint32_t)(2*MATB + (wn*32 + rowB) * RS + colB);
    uint32_t offBl = offBh + MATB;

    const __half* srcs[4] = {Ah, Al, Bh, Bl};

    float acc[MT*4][4];
#pragma unroll
    for (int i = 0; i < MT*4; i++) { acc[i][0]=acc[i][1]=acc[i][2]=acc[i][3]=0.f; }

    auto load_stage = [&](int stage, int k0) {
        uint32_t dstb = sbase + stage * STAGEB;
#pragma unroll
        for (int it = 0; it < BM/32; it++) {        // A: 2 mats x BM rows x 4
            int c = tid + it * 256;
            int mat = (c >= BM*4) ? 1 : 0;
            int r = (c >> 2) & (BM - 1), cc = c & 3;
            const __half* src = srcs[mat] + (size_t)(m0 + r) * K + k0 + cc * 8;
            cp16(dstb + mat*MATB + r*RS + cc*16, src);
        }
#pragma unroll
        for (int it = 0; it < 4; it++) {            // B: 2 mats x 128 rows x 4
            int c = tid + it * 256;
            int mat = 2 + (c >> 9);
            int r = (c >> 2) & 127, cc = c & 3;
            const __half* src = srcs[mat] + (size_t)(nb0 + r) * K + k0 + cc * 8;
            cp16(dstb + mat*MATB + r*RS + cc*16, src);
        }
        CP_COMMIT();
    };

    auto compute = [&](int stage) {
        uint32_t st = sbase + stage * STAGEB;
        uint32_t uAh = st + offAh, uAl = st + offAl;
        uint32_t uBh = st + offBh, uBl = st + offBl;
#pragma unroll
        for (int ks = 0; ks < 2; ks++) {
            uint32_t bh[4][2], bl[4][2];
#pragma unroll
            for (int np = 0; np < 2; np++) {
                uint32_t t[4];
                ldsm4(t, uBh + np*(16*RS) + ks*32);
                bh[2*np][0]=t[0]; bh[2*np][1]=t[1];
                bh[2*np+1][0]=t[2]; bh[2*np+1][1]=t[3];
                ldsm4(t, uBl + np*(16*RS) + ks*32);
                bl[2*np][0]=t[0]; bl[2*np][1]=t[1];
                bl[2*np+1][0]=t[2]; bl[2*np+1][1]=t[3];
            }
            uint32_t a[MT][4];
#pragma unroll
            for (int mt = 0; mt < MT; mt++)
                ldsm4(a[mt], uAh + mt*(16*RS) + ks*32);
#pragma unroll
            for (int mt = 0; mt < MT; mt++)
#pragma unroll
                for (int nt = 0; nt < 4; nt++)
                    mma16816(acc[mt*4+nt], a[mt], bh[nt]);
#pragma unroll
            for (int mt = 0; mt < MT; mt++)
#pragma unroll
                for (int nt = 0; nt < 4; nt++)
                    mma16816(acc[mt*4+nt], a[mt], bl[nt]);
#pragma unroll
            for (int mt = 0; mt < MT; mt++)
                ldsm4(a[mt], uAl + mt*(16*RS) + ks*32);
#pragma unroll
            for (int mt = 0; mt < MT; mt++)
#pragma unroll
                for (int nt = 0; nt < 4; nt++)
                    mma16816(acc[mt*4+nt], a[mt], bh[nt]);
        }
    };

    const int nChunks = K >> 5;
    load_stage(0, 0);
    for (int c = 0; c < nChunks; c++) {
        CP_WAIT(0);          // own-group load(c) done
        __syncthreads();     // publishes load(c); all warps past compute(c-1)
        if (c + 1 < nChunks) load_stage((c + 1) & 1, (c + 1) * 32);
        compute(c & 1);      // stage c&1; overwritten only after next top-sync
    }

#pragma unroll
    for (int mt = 0; mt < MT; mt++) {
#pragma unroll
        for (int nt = 0; nt < 4; nt++) {
            float* ac = acc[mt*4+nt];
            int nb = n0 + wn*32 + nt*8 + (lane & 3)*2;
#pragma unroll
            for (int hh = 0; hh < 2; hh++) {
                int m = m0 + wm*(BM/2) + mt*16 + (lane >> 2) + hh*8;
                if (MODE == 0) {
                    float v0 = ac[2*hh] + bias[nb], v1 = ac[2*hh+1] + bias[nb+1];
                    *(float2*)(C + (size_t)m * N + nb) = make_float2(v0, v1);
                } else {
                    int tg = m >> 2, bb = m & 3;
                    if (nb < 3*En) {
                        float v0 = ac[2*hh] + bias[nb], v1 = ac[2*hh+1] + bias[nb+1];
                        int part = nb >> 10, e = nb & 1023;
                        int hd = e >> 6, dd = e & 63;
                        if (part == 0) { v0 *= 0.125f*LOG2E; v1 *= 0.125f*LOG2E; }
                        uint32_t hi, lo;
                        split2(v0, v1, hi, lo);
                        size_t off = ((size_t)(bb*Hn + hd) * TGTn + tg) * HDn + dd;
                        __half *dh, *dl;
                        if (part == 0)      { dh = g_q_h; dl = g_q_l; }
                        else if (part == 1) { dh = g_k_h; dl = g_k_l; }
                        else                { dh = g_v_h; dl = g_v_l; }
                        *(uint32_t*)(dh + off) = hi;
                        *(uint32_t*)(dl + off) = lo;
                    } else {
                        int col = nb - 3*En;
                        float v0 = (ac[2*hh]   + bias2[col])   * LOG2E;
                        float v1 = (ac[2*hh+1] + bias2[col+1]) * LOG2E;
                        g_vals[(((size_t)bb*TGTn + tg)*Hn + (col & 15))*NBn + (col >> 4)]     = v0;
                        g_vals[(((size_t)bb*TGTn + tg)*Hn + ((col+1) & 15))*NBn + ((col+1) >> 4)] = v1;
                    }
                }
            }
        }
    }
}

// ---------------------------------------------------------------------------
// HMMA flash attention v5: register Q frags, cp.async double-buffered K/V,
// single sync per tile, exp2 softmax, causal-only + warp skip, SIMT diag.
// ---------------------------------------------------------------------------
#define ARS 144
#define KVSTAGE 36864                 // 4 mats x 64 rows x 144 B
#define O_VALS (2*KVSTAGE)            // 73728
#define SM_ATTN (O_VALS + 128*32*4)   // 90112

__global__ __launch_bounds__(256, 2) void attn3(
    const int* __restrict__ main_buckets,
    const int* __restrict__ pred_buckets)
{
    extern __shared__ __align__(16) char smem[];
    float* sVals = (float*)(smem + O_VALS);
    uint32_t sbase = smem_u32(smem);

    int tid = threadIdx.x, lane = tid & 31, w = tid >> 5;
    int tileX = blockIdx.x;              // 0..3
    int bh = blockIdx.y;                 // 0..63
    int var = blockIdx.z;                // 0 main, 1..2 ngram
    int b = bh >> 4, h = bh & 15;
    int qoff = (var == 0) ? 0 : (Tn + (var - 1) * Tn);
    int t0 = tileX * 128;
    int nTiles = 2*tileX + 2;

    const __half* gkv[4] = {g_k_h, g_k_l, g_v_h, g_v_l};

    // ---- prologue: async-load K/V tile 0 into stage 0 ----
#pragma unroll
    for (int it = 0; it < 8; it++) {
        int s = tid + it * 256;
        int buf = s >> 9, r = (s >> 3) & 63, cc = s & 7;
        const __half* src = gkv[buf] + ((size_t)bh * TGTn + r) * HDn + cc * 8;
        cp16(sbase + buf*9216 + r*ARS + cc*16, src);
    }
    CP_COMMIT();

    // ---- stage Q (hi/lo) into stage-1 area, plus sVals ----
#pragma unroll
    for (int it = 0; it < 8; it++) {
        int s = tid + it * 256;
        int buf = s >> 10, r = (s >> 3) & 127, cc = s & 7;
        const __half* src = (buf ? g_q_l : g_q_h)
            + ((size_t)bh * TGTn + qoff + t0 + r) * HDn + cc * 8;
        *(uint4*)(smem + KVSTAGE + buf*18432 + r*ARS + cc*16) = *(const uint4*)src;
    }
#pragma unroll
    for (int it = 0; it < 4; it++) {
        int s = tid + it * 256;
        int r = s >> 3, cc = s & 7;
        const float* src = g_vals
            + (((size_t)b * TGTn + qoff + t0 + r) * Hn + h) * NBn + cc * 4;
        *(float4*)(sVals + r*32 + cc*4) = *(const float4*)src;
    }
    __syncthreads();

    // ---- extract Q fragments into registers ----
    int rowA = (lane & 7) + ((lane >> 3) & 1) * 8;
    int colA = ((lane >> 4) & 1) * 16;
    uint32_t aQh = sbase + KVSTAGE + (uint32_t)((16*w + rowA)*ARS + colA);
    uint32_t aQl = aQh + 18432;
    uint32_t qh[4][4], ql[4][4];
#pragma unroll
    for (int kk = 0; kk < 4; kk++) {
        ldsm4(qh[kk], aQh + kk*32);
        ldsm4(ql[kk], aQl + kk*32);
    }
    // no sync needed here: first loop iteration's top sync protects the
    // stage-1 area before any prefetch overwrites it.

    int rowB = (lane & 7) + ((lane >> 4) & 1) * 8;
    int colB = ((lane >> 3) & 1) * 16;
    int rowV = (lane & 7) + ((lane >> 3) & 1) * 8;
    int colV = ((lane >> 4) & 1) * 16;

    const int* bbase;
    int bstr;
    if (var == 0) { bbase = main_buckets + (size_t)b * Tn * Tn;      bstr = Tn;   }
    else          { bbase = pred_buckets + (size_t)b * Tn * 2 * Tn;  bstr = 2*Tn; }

    float m_[2] = {-1e30f, -1e30f}, l_[2] = {0.f, 0.f};
    float o[8][4];
#pragma unroll
    for (int j = 0; j < 8; j++) { o[j][0]=o[j][1]=o[j][2]=o[j][3]=0.f; }

    int qrow0 = (lane >> 2);
    int lim = t0 + 16*w + 15;

    for (int st = 0; st < nTiles; st++) {
        int s0 = st * 64;
        CP_WAIT(0);          // own-group load(st) done
        __syncthreads();     // publish; all warps past compute(st-1)
        // prefetch next tile into the other stage (overwrites stage st-1's,
        // or on st=0 the Q staging area — both protected by the sync above)
        if (st + 1 < nTiles) {
            int s1 = s0 + 64;
#pragma unroll
            for (int it = 0; it < 8; it++) {
                int s = tid + it * 256;
                int buf = s >> 9, r = (s >> 3) & 63, cc = s & 7;
                const __half* src = gkv[buf]
                    + ((size_t)bh * TGTn + s1 + r) * HDn + cc * 8;
                cp16(sbase + ((st+1)&1)*KVSTAGE + buf*9216 + r*ARS + cc*16, src);
            }
            CP_COMMIT();
        }

        if (s0 <= lim) {
            uint32_t kvb = sbase + (st & 1)*KVSTAGE;
            uint32_t aKh = kvb + (uint32_t)(rowB*ARS + colB);
            uint32_t aKl = aKh + 9216;
            uint32_t aVh = kvb + 18432 + (uint32_t)(rowV*ARS + colV);
            uint32_t aVl = aVh + 9216;

            bool jskip[8];
#pragma unroll
            for (int j = 0; j < 8; j++) jskip[j] = (s0 + 8*j > lim);

            // ---- scores ----
            float sc[8][4];
#pragma unroll
            for (int j = 0; j < 8; j++) { sc[j][0]=sc[j][1]=sc[j][2]=sc[j][3]=0.f; }
#pragma unroll
            for (int kk = 0; kk < 4; kk++) {
#pragma unroll
                for (int np = 0; np < 4; np++) {
                    if (jskip[2*np]) continue;
                    uint32_t th[4], tl[4];
                    ldsm4(th, aKh + np*(16*ARS) + kk*32);
                    ldsm4(tl, aKl + np*(16*ARS) + kk*32);
                    mma16816(sc[2*np],   qh[kk], th);
                    mma16816(sc[2*np+1], qh[kk], th+2);
                    mma16816(sc[2*np],   ql[kk], th);
                    mma16816(sc[2*np+1], ql[kk], th+2);
                    mma16816(sc[2*np],   qh[kk], tl);
                    mma16816(sc[2*np+1], qh[kk], tl+2);
                }
            }

            // ---- bias gather + causal mask ----
#pragma unroll
            for (int j = 0; j < 8; j++) {
                if (jskip[j]) continue;
                int coll = 8*j + (lane & 3)*2;
#pragma unroll
                for (int hh = 0; hh < 2; hh++) {
                    int qr = 16*w + qrow0 + 8*hh;
                    int2 bk = *(const int2*)(bbase + (size_t)(t0 + qr) * bstr + s0 + coll);
                    bool v0 = (s0 + coll)     <= (t0 + qr);
                    bool v1 = (s0 + coll + 1) <= (t0 + qr);
                    sc[j][2*hh]   = v0 ? (sc[j][2*hh]   + sVals[qr*32 + bk.x]) : -1e30f;
                    sc[j][2*hh+1] = v1 ? (sc[j][2*hh+1] + sVals[qr*32 + bk.y]) : -1e30f;
                }
            }

            // ---- online softmax (base-2) ----
#pragma unroll
            for (int hh = 0; hh < 2; hh++) {
                float rm = -1e30f;
#pragma unroll
                for (int j = 0; j < 8; j++)
                    if (!jskip[j]) rm = fmaxf(rm, fmaxf(sc[j][2*hh], sc[j][2*hh+1]));
                rm = fmaxf(rm, __shfl_xor_sync(0xffffffffu, rm, 1));
                rm = fmaxf(rm, __shfl_xor_sync(0xffffffffu, rm, 2));
                float mnew = fmaxf(m_[hh], rm);
                float scale = ex2(m_[hh] - mnew);
                float sum = 0.f;
#pragma unroll
                for (int j = 0; j < 8; j++) {
                    if (jskip[j]) { sc[j][2*hh] = 0.f; sc[j][2*hh+1] = 0.f; continue; }
                    float p0 = ex2(sc[j][2*hh]   - mnew);
                    float p1 = ex2(sc[j][2*hh+1] - mnew);
                    sc[j][2*hh] = p0; sc[j][2*hh+1] = p1;
                    sum += p0 + p1;
                }
                sum += __shfl_xor_sync(0xffffffffu, sum, 1);
                sum += __shfl_xor_sync(0xffffffffu, sum, 2);
                l_[hh] = l_[hh] * scale + sum;
                m_[hh] = mnew;
#pragma unroll
                for (int j = 0; j < 8; j++) {
                    o[j][2*hh]   *= scale;
                    o[j][2*hh+1] *= scale;
                }
            }

            // ---- O += P V ----
#pragma unroll
            for (int kk2 = 0; kk2 < 4; kk2++) {
                if (jskip[2*kk2]) continue;
                uint32_t ahi[4], alo[4];
                split2(sc[2*kk2][0],   sc[2*kk2][1],   ahi[0], alo[0]);
                split2(sc[2*kk2][2],   sc[2*kk2][3],   ahi[1], alo[1]);
                split2(sc[2*kk2+1][0], sc[2*kk2+1][1], ahi[2], alo[2]);
                split2(sc[2*kk2+1][2], sc[2*kk2+1][3], ahi[3], alo[3]);
#pragma unroll
                for (int ng = 0; ng < 4; ng++) {
                    uint32_t vh4[4], vl4[4];
                    ldsm4t(vh4, aVh + kk2*(16*ARS) + ng*32);
                    ldsm4t(vl4, aVl + kk2*(16*ARS) + ng*32);
                    mma16816(o[2*ng],   ahi, vh4);
                    mma16816(o[2*ng+1], ahi, vh4+2);
                    mma16816(o[2*ng],   alo, vh4);
                    mma16816(o[2*ng+1], alo, vh4+2);
                    mma16816(o[2*ng],   ahi, vl4);
                    mma16816(o[2*ng+1], ahi, vl4+2);
                }
            }
        }
    }

    // ---- ngram diagonal key: SIMT scalar merge ----
    if (var != 0) {
#pragma unroll
        for (int hh = 0; hh < 2; hh++) {
            int qr = 16*w + qrow0 + 8*hh;
            int t = t0 + qr;
            size_t rowoff = ((size_t)bh * TGTn + qoff + t) * HDn;
            size_t doff = rowoff + (lane & 3) * 16;
            float dot = 0.f;
#pragma unroll
            for (int u = 0; u < 2; u++) {
                uint4 qh4 = *(const uint4*)(g_q_h + doff + u*8);
                uint4 ql4 = *(const uint4*)(g_q_l + doff + u*8);
                uint4 kh4 = *(const uint4*)(g_k_h + doff + u*8);
                uint4 kl4 = *(const uint4*)(g_k_l + doff + u*8);
                const uint32_t* qh_ = &qh4.x; const uint32_t* ql_ = &ql4.x;
                const uint32_t* kh_ = &kh4.x; const uint32_t* kl_ = &kl4.x;
#pragma unroll
                for (int c = 0; c < 4; c++) {
                    float2 qv = h2sum(qh_[c], ql_[c]);
                    float2 kv = h2sum(kh_[c], kl_[c]);
                    dot += qv.x*kv.x + qv.y*kv.y;
                }
            }
            dot += __shfl_xor_sync(0xffffffffu, dot, 1);
            dot += __shfl_xor_sync(0xffffffffu, dot, 2);
            int bkt = bbase[(size_t)t * bstr + Tn + t];
            float sd = dot + sVals[qr*32 + bkt];

            float mnew = fmaxf(m_[hh], sd);
            float scale = ex2(m_[hh] - mnew);
            float pd = ex2(sd - mnew);
            l_[hh] = l_[hh] * scale + pd;
            m_[hh] = mnew;
#pragma unroll
            for (int j = 0; j < 8; j++) {
                int col = 8*j + (lane & 3)*2;
                uint32_t vh = *(const uint32_t*)(g_v_h + rowoff + col);
                uint32_t vl = *(const uint32_t*)(g_v_l + rowoff + col);
                float2 vv = h2sum(vh, vl);
                o[j][2*hh]   = o[j][2*hh]   * scale + pd * vv.x;
                o[j][2*hh+1] = o[j][2*hh+1] * scale + pd * vv.y;
            }
        }
    }

    // ---- epilogue: ctx (fp16 hi/lo) = O / l ----
#pragma unroll
    for (int hh = 0; hh < 2; hh++) {
        int qr = 16*w + qrow0 + 8*hh;
        int tg = qoff + t0 + qr;
        float inv = 1.0f / l_[hh];
#pragma unroll
        for (int j = 0; j < 8; j++) {
            int col = 8*j + (lane & 3)*2;
            float x0 = o[j][2*hh] * inv, x1 = o[j][2*hh+1] * inv;
            uint32_t hi, lo;
            split2(x0, x1, hi, lo);
            size_t off = ((size_t)tg * Bn + b) * En + h * HDn + col;
            *(uint32_t*)(g_ctx_h + off) = hi;
            *(uint32_t*)(g_ctx_l + off) = lo;
        }
    }
}

// ---------------------------------------------------------------------------
extern "C" void kernel_launch(void* const* d_in, const int* in_sizes, int n_in,
                              void* d_out, int out_size) {
    const float* query = (const float*)d_in[0];
    const float* ipw   = (const float*)d_in[1];
    const float* ipb   = (const float*)d_in[2];
    const float* relw  = (const float*)d_in[3];
    const float* relb  = (const float*)d_in[4];
    const float* outw  = (const float*)d_in[5];
    const float* outb  = (const float*)d_in[6];
    const int*   mb    = (const int*)d_in[7];
    const int*   pb    = (const int*)d_in[8];
    float* out = (float*)d_out;

    cudaFuncSetAttribute((const void*)hgemm2<0,64>,
                         cudaFuncAttributeMaxDynamicSharedMemorySize, SM_GEMM);
    cudaFuncSetAttribute((const void*)hgemm2<1,128>,
                         cudaFuncAttributeMaxDynamicSharedMemorySize, SM_GEMM);
    cudaFuncSetAttribute((const void*)attn3,
                         cudaFuncAttributeMaxDynamicSharedMemorySize, SM_ATTN);

    // 0) fused pre-convert
    convert_all<<<10752, 256>>>(query, ipw, relw, outw);
    // 1) qkv + rel-vals projection (merged, N = 3072 + 512)
    hgemm2<1,128><<<dim3(28, 48), 256, SM_GEMM>>>(ipb, relb, nullptr, Mrows, 3*En + NBn*Hn, En);
    // 2) fused HMMA flash attention
    attn3<<<dim3(4, 64, 3), 256, SM_ATTN>>>(mb, pb);
    // 3) output projection -> d_out (BM=64: 768 blocks for wave balance)
    hgemm2<0,64><<<dim3(8, 96), 256, SM_GEMM>>>(outb, nullptr, out, Mrows, En, En);
}

// round 13
// speedup vs baseline: 1.0250x; 1.0250x over previous
#include <cuda_runtime.h>
#include <cuda_fp16.h>
#include <cstdint>

#define Tn    512
#define Bn    4
#define En    1024
#define Hn    16
#define HDn   64
#define NBn   32
#define TGTn  1536
#define BHn   64
#define Mrows (TGTn*Bn)   /* 6144 */
#define LOG2E 1.442695041f

// -------- scratch (static device globals) --------
__device__ __half g_x_h[(size_t)Mrows*En],    g_x_l[(size_t)Mrows*En];
__device__ __half g_ipw_h[(size_t)3*En*En],   g_ipw_l[(size_t)3*En*En];
__device__ __half g_relw_h[(size_t)NBn*Hn*En],g_relw_l[(size_t)NBn*Hn*En];
__device__ __half g_outw_h[(size_t)En*En],    g_outw_l[(size_t)En*En];
__device__ __half g_ctx_h[(size_t)Mrows*En],  g_ctx_l[(size_t)Mrows*En];
__device__ __half g_q_h[(size_t)BHn*TGTn*HDn], g_q_l[(size_t)BHn*TGTn*HDn];
__device__ __half g_k_h[(size_t)BHn*TGTn*HDn], g_k_l[(size_t)BHn*TGTn*HDn];
__device__ __half g_v_h[(size_t)BHn*TGTn*HDn], g_v_l[(size_t)BHn*TGTn*HDn];
__device__ float  g_vals[(size_t)Bn*TGTn*Hn*NBn];   // [b][tg][h][nb], pre-scaled by LOG2E

// ============================ helpers ==================================
__device__ __forceinline__ uint32_t smem_u32(const void* p) {
    uint32_t a;
    asm("{ .reg .u64 t; cvta.to.shared.u64 t, %1; cvt.u32.u64 %0, t; }"
        : "=r"(a) : "l"(p));
    return a;
}
__device__ __forceinline__ void ldsm4(uint32_t* r, uint32_t addr) {
    asm volatile("ldmatrix.sync.aligned.m8n8.x4.shared.b16 {%0,%1,%2,%3}, [%4];"
                 : "=r"(r[0]), "=r"(r[1]), "=r"(r[2]), "=r"(r[3]) : "r"(addr));
}
__device__ __forceinline__ void ldsm4t(uint32_t* r, uint32_t addr) {
    asm volatile("ldmatrix.sync.aligned.m8n8.x4.trans.shared.b16 {%0,%1,%2,%3}, [%4];"
                 : "=r"(r[0]), "=r"(r[1]), "=r"(r[2]), "=r"(r[3]) : "r"(addr));
}
__device__ __forceinline__ void mma16816(float* c, const uint32_t* a, const uint32_t* b) {
    asm volatile(
        "mma.sync.aligned.m16n8k16.row.col.f32.f16.f16.f32 "
        "{%0,%1,%2,%3}, {%4,%5,%6,%7}, {%8,%9}, {%0,%1,%2,%3};"
        : "+f"(c[0]), "+f"(c[1]), "+f"(c[2]), "+f"(c[3])
        : "r"(a[0]), "r"(a[1]), "r"(a[2]), "r"(a[3]), "r"(b[0]), "r"(b[1]));
}
__device__ __forceinline__ void cp16(uint32_t dst, const void* src) {
    asm volatile("cp.async.cg.shared.global [%0], [%1], 16;"
                 :: "r"(dst), "l"(src) : "memory");
}
#define CP_COMMIT() asm volatile("cp.async.commit_group;" ::: "memory")
#define CP_WAIT(N)  asm volatile("cp.async.wait_group %0;" :: "n"(N) : "memory")

__device__ __forceinline__ void split2(float x, float y, uint32_t& hi, uint32_t& lo) {
    __half hx = __float2half_rn(x), hy = __float2half_rn(y);
    __half lx = __float2half_rn(x - __half2float(hx));
    __half ly = __float2half_rn(y - __half2float(hy));
    __half2 h = __halves2half2(hx, hy), l = __halves2half2(lx, ly);
    hi = *(uint32_t*)&h; lo = *(uint32_t*)&l;
}
__device__ __forceinline__ float2 h2sum(uint32_t h, uint32_t l) {
    float2 a = __half22float2(*(__half2*)&h);
    float2 b = __half22float2(*(__half2*)&l);
    return make_float2(a.x + b.x, a.y + b.y);
}
__device__ __forceinline__ float ex2(float x) {
    float r;
    asm("ex2.approx.ftz.f32 %0, %1;" : "=f"(r) : "f"(x));
    return r;
}

// ---------------------------------------------------------------------------
// Fused pre-convert: f32 -> fp16 hi/lo for all four operand tensors.
// ---------------------------------------------------------------------------
__global__ __launch_bounds__(256) void convert_all(
    const float* __restrict__ q, const float* __restrict__ w1,
    const float* __restrict__ w2, const float* __restrict__ w3)
{
    int bid = blockIdx.x;
    const float* src; __half *dh, *dl; int lb;
    if (bid < 6144)      { src = q;  dh = g_x_h;    dl = g_x_l;    lb = bid; }
    else if (bid < 9216) { src = w1; dh = g_ipw_h;  dl = g_ipw_l;  lb = bid - 6144; }
    else if (bid < 9728) { src = w2; dh = g_relw_h; dl = g_relw_l; lb = bid - 9216; }
    else                 { src = w3; dh = g_outw_h; dl = g_outw_l; lb = bid - 9728; }
    int i = (lb * 256 + threadIdx.x) * 4;
    float4 v = *(const float4*)(src + i);
    uint32_t h01, l01, h23, l23;
    split2(v.x, v.y, h01, l01);
    split2(v.z, v.w, h23, l23);
    *(uint2*)(dh + i) = make_uint2(h01, h23);
    *(uint2*)(dl + i) = make_uint2(l01, l23);
}

// ---------------------------------------------------------------------------
// HMMA GEMM (fp16 split 3-pass, cp.async 2-stage, single sync per chunk).
// BM=BN=128, BK=32, 256 threads (8 warps, 2x4 warp grid, 64x32 warp tile).
// MODE 0: A=g_ctx, B=g_outw -> C (fp32)
// MODE 1: A=g_x, B=[g_ipw | g_relw] (N=3584). Cols <3072 -> q/k/v scatter
//         (q scaled 0.125*LOG2E); cols >=3072 -> g_vals (scaled LOG2E).
// ---------------------------------------------------------------------------
#define RS 80
#define MATB (128*RS)
#define STAGEB (4*MATB)
#define SM_GEMM (2*STAGEB)

template<int MODE>
__global__ __launch_bounds__(256, 2) void hgemm2(
    const float* __restrict__ bias, const float* __restrict__ bias2,
    float* __restrict__ C, int M, int N, int K)
{
    extern __shared__ __align__(16) char smem[];
    const __half* Ah = (MODE == 0) ? g_ctx_h : g_x_h;
    const __half* Al = (MODE == 0) ? g_ctx_l : g_x_l;

    int tid = threadIdx.x, lane = tid & 31, wid = tid >> 5;
    int wm = wid & 1, wn = wid >> 1;
    int m0 = blockIdx.y * 128, n0 = blockIdx.x * 128;
    uint32_t sbase = smem_u32(smem);

    const __half *Bh, *Bl; int nb0;
    if (MODE == 1 && n0 >= 3*En) { Bh = g_relw_h; Bl = g_relw_l; nb0 = n0 - 3*En; }
    else if (MODE == 1)          { Bh = g_ipw_h;  Bl = g_ipw_l;  nb0 = n0; }
    else                         { Bh = g_outw_h; Bl = g_outw_l; nb0 = n0; }

    int rowA = (lane & 7) + ((lane >> 3) & 1) * 8;
    int colA = ((lane >> 4) & 1) * 16;
    int rowB = (lane & 7) + ((lane >> 4) & 1) * 8;
    int colB = ((lane >> 3) & 1) * 16;
    uint32_t offAh = (uint32_t)((wm*64 + rowA) * RS + colA);
    uint32_t offAl = offAh + MATB;
    uint32_t offBh = (uint32_t)(2*MATB + (wn*32 + rowB) * RS + colB);
    uint32_t offBl = offBh + MATB;

    const __half* srcs[4] = {Ah, Al, Bh, Bl};

    float acc[16][4];
#pragma unroll
    for (int i = 0; i < 16; i++) { acc[i][0]=acc[i][1]=acc[i][2]=acc[i][3]=0.f; }

    auto load_stage = [&](int stage, int k0) {
        uint32_t dstb = sbase + stage * STAGEB;
#pragma unroll
        for (int it = 0; it < 8; it++) {
            int c = tid + it * 256;                 // 2048 16B chunks
            int mat = c >> 9, r = (c >> 2) & 127, cc = c & 3;
            int grow = ((mat < 2) ? m0 : nb0) + r;
            const __half* src = srcs[mat] + (size_t)grow * K + k0 + cc * 8;
            cp16(dstb + mat*MATB + r*RS + cc*16, src);
        }
        CP_COMMIT();
    };

    auto compute = [&](int stage) {
        uint32_t st = sbase + stage * STAGEB;
        uint32_t uAh = st + offAh, uAl = st + offAl;
        uint32_t uBh = st + offBh, uBl = st + offBl;
#pragma unroll
        for (int ks = 0; ks < 2; ks++) {
            uint32_t bh[4][2], bl[4][2];
#pragma unroll
            for (int np = 0; np < 2; np++) {
                uint32_t t[4];
                ldsm4(t, uBh + np*(16*RS) + ks*32);
                bh[2*np][0]=t[0]; bh[2*np][1]=t[1];
                bh[2*np+1][0]=t[2]; bh[2*np+1][1]=t[3];
                ldsm4(t, uBl + np*(16*RS) + ks*32);
                bl[2*np][0]=t[0]; bl[2*np][1]=t[1];
                bl[2*np+1][0]=t[2]; bl[2*np+1][1]=t[3];
            }
            uint32_t a[4][4];
#pragma unroll
            for (int mt = 0; mt < 4; mt++)
                ldsm4(a[mt], uAh + mt*(16*RS) + ks*32);
#pragma unroll
            for (int mt = 0; mt < 4; mt++)
#pragma unroll
                for (int nt = 0; nt < 4; nt++)
                    mma16816(acc[mt*4+nt], a[mt], bh[nt]);
#pragma unroll
            for (int mt = 0; mt < 4; mt++)
#pragma unroll
                for (int nt = 0; nt < 4; nt++)
                    mma16816(acc[mt*4+nt], a[mt], bl[nt]);
#pragma unroll
            for (int mt = 0; mt < 4; mt++)
                ldsm4(a[mt], uAl + mt*(16*RS) + ks*32);
#pragma unroll
            for (int mt = 0; mt < 4; mt++)
#pragma unroll
                for (int nt = 0; nt < 4; nt++)
                    mma16816(acc[mt*4+nt], a[mt], bh[nt]);
        }
    };

    const int nChunks = K >> 5;
    load_stage(0, 0);
    for (int c = 0; c < nChunks; c++) {
        CP_WAIT(0);          // own-group load(c) done
        __syncthreads();     // publishes load(c); all warps past compute(c-1)
        if (c + 1 < nChunks) load_stage((c + 1) & 1, (c + 1) * 32);
        compute(c & 1);      // stage c&1; overwritten only after next top-sync
    }

#pragma unroll
    for (int mt = 0; mt < 4; mt++) {
#pragma unroll
        for (int nt = 0; nt < 4; nt++) {
            float* ac = acc[mt*4+nt];
            int nb = n0 + wn*32 + nt*8 + (lane & 3)*2;
#pragma unroll
            for (int hh = 0; hh < 2; hh++) {
                int m = m0 + wm*64 + mt*16 + (lane >> 2) + hh*8;
                if (MODE == 0) {
                    float v0 = ac[2*hh] + bias[nb], v1 = ac[2*hh+1] + bias[nb+1];
                    *(float2*)(C + (size_t)m * N + nb) = make_float2(v0, v1);
                } else {
                    int tg = m >> 2, bb = m & 3;
                    if (nb < 3*En) {
                        float v0 = ac[2*hh] + bias[nb], v1 = ac[2*hh+1] + bias[nb+1];
                        int part = nb >> 10, e = nb & 1023;
                        int hd = e >> 6, dd = e & 63;
                        if (part == 0) { v0 *= 0.125f*LOG2E; v1 *= 0.125f*LOG2E; }
                        uint32_t hi, lo;
                        split2(v0, v1, hi, lo);
                        size_t off = ((size_t)(bb*Hn + hd) * TGTn + tg) * HDn + dd;
                        __half *dh, *dl;
                        if (part == 0)      { dh = g_q_h; dl = g_q_l; }
                        else if (part == 1) { dh = g_k_h; dl = g_k_l; }
                        else                { dh = g_v_h; dl = g_v_l; }
                        *(uint32_t*)(dh + off) = hi;
                        *(uint32_t*)(dl + off) = lo;
                    } else {
                        int col = nb - 3*En;
                        float v0 = (ac[2*hh]   + bias2[col])   * LOG2E;
                        float v1 = (ac[2*hh+1] + bias2[col+1]) * LOG2E;
                        g_vals[(((size_t)bb*TGTn + tg)*Hn + (col & 15))*NBn + (col >> 4)]     = v0;
                        g_vals[(((size_t)bb*TGTn + tg)*Hn + ((col+1) & 15))*NBn + ((col+1) >> 4)] = v1;
                    }
                }
            }
        }
    }
}

// ---------------------------------------------------------------------------
// HMMA flash attention v5: register Q frags, cp.async double-buffered K/V,
// single sync per tile, exp2 softmax, causal-only + warp skip, SIMT diag.
// ---------------------------------------------------------------------------
#define ARS 144
#define KVSTAGE 36864                 // 4 mats x 64 rows x 144 B
#define O_VALS (2*KVSTAGE)            // 73728
#define SM_ATTN (O_VALS + 128*32*4)   // 90112

__global__ __launch_bounds__(256, 2) void attn3(
    const int* __restrict__ main_buckets,
    const int* __restrict__ pred_buckets)
{
    extern __shared__ __align__(16) char smem[];
    float* sVals = (float*)(smem + O_VALS);
    uint32_t sbase = smem_u32(smem);

    int tid = threadIdx.x, lane = tid & 31, w = tid >> 5;
    int tileX = blockIdx.x;              // 0..3
    int bh = blockIdx.y;                 // 0..63
    int var = blockIdx.z;                // 0 main, 1..2 ngram
    int b = bh >> 4, h = bh & 15;
    int qoff = (var == 0) ? 0 : (Tn + (var - 1) * Tn);
    int t0 = tileX * 128;
    int nTiles = 2*tileX + 2;

    const __half* gkv[4] = {g_k_h, g_k_l, g_v_h, g_v_l};

    // ---- prologue: async-load K/V tile 0 into stage 0 ----
#pragma unroll
    for (int it = 0; it < 8; it++) {
        int s = tid + it * 256;
        int buf = s >> 9, r = (s >> 3) & 63, cc = s & 7;
        const __half* src = gkv[buf] + ((size_t)bh * TGTn + r) * HDn + cc * 8;
        cp16(sbase + buf*9216 + r*ARS + cc*16, src);
    }
    CP_COMMIT();

    // ---- stage Q (hi/lo) into stage-1 area, plus sVals ----
#pragma unroll
    for (int it = 0; it < 8; it++) {
        int s = tid + it * 256;
        int buf = s >> 10, r = (s >> 3) & 127, cc = s & 7;
        const __half* src = (buf ? g_q_l : g_q_h)
            + ((size_t)bh * TGTn + qoff + t0 + r) * HDn + cc * 8;
        *(uint4*)(smem + KVSTAGE + buf*18432 + r*ARS + cc*16) = *(const uint4*)src;
    }
#pragma unroll
    for (int it = 0; it < 4; it++) {
        int s = tid + it * 256;
        int r = s >> 3, cc = s & 7;
        const float* src = g_vals
            + (((size_t)b * TGTn + qoff + t0 + r) * Hn + h) * NBn + cc * 4;
        *(float4*)(sVals + r*32 + cc*4) = *(const float4*)src;
    }
    __syncthreads();

    // ---- extract Q fragments into registers ----
    int rowA = (lane & 7) + ((lane >> 3) & 1) * 8;
    int colA = ((lane >> 4) & 1) * 16;
    uint32_t aQh = sbase + KVSTAGE + (uint32_t)((16*w + rowA)*ARS + colA);
    uint32_t aQl = aQh + 18432;
    uint32_t qh[4][4], ql[4][4];
#pragma unroll
    for (int kk = 0; kk < 4; kk++) {
        ldsm4(qh[kk], aQh + kk*32);
        ldsm4(ql[kk], aQl + kk*32);
    }
    // first loop iteration's top sync protects the stage-1 area before
    // any prefetch overwrites it.

    int rowB = (lane & 7) + ((lane >> 4) & 1) * 8;
    int colB = ((lane >> 3) & 1) * 16;
    int rowV = (lane & 7) + ((lane >> 3) & 1) * 8;
    int colV = ((lane >> 4) & 1) * 16;

    const int* bbase;
    int bstr;
    if (var == 0) { bbase = main_buckets + (size_t)b * Tn * Tn;      bstr = Tn;   }
    else          { bbase = pred_buckets + (size_t)b * Tn * 2 * Tn;  bstr = 2*Tn; }

    float m_[2] = {-1e30f, -1e30f}, l_[2] = {0.f, 0.f};
    float o[8][4];
#pragma unroll
    for (int j = 0; j < 8; j++) { o[j][0]=o[j][1]=o[j][2]=o[j][3]=0.f; }

    int qrow0 = (lane >> 2);
    int lim = t0 + 16*w + 15;

    for (int st = 0; st < nTiles; st++) {
        int s0 = st * 64;
        CP_WAIT(0);          // own-group load(st) done
        __syncthreads();     // publish; all warps past compute(st-1)
        if (st + 1 < nTiles) {
            int s1 = s0 + 64;
#pragma unroll
            for (int it = 0; it < 8; it++) {
                int s = tid + it * 256;
                int buf = s >> 9, r = (s >> 3) & 63, cc = s & 7;
                const __half* src = gkv[buf]
                    + ((size_t)bh * TGTn + s1 + r) * HDn + cc * 8;
                cp16(sbase + ((st+1)&1)*KVSTAGE + buf*9216 + r*ARS + cc*16, src);
            }
            CP_COMMIT();
        }

        if (s0 <= lim) {
            uint32_t kvb = sbase + (st & 1)*KVSTAGE;
            uint32_t aKh = kvb + (uint32_t)(rowB*ARS + colB);
            uint32_t aKl = aKh + 9216;
            uint32_t aVh = kvb + 18432 + (uint32_t)(rowV*ARS + colV);
            uint32_t aVl = aVh + 9216;

            bool jskip[8];
#pragma unroll
            for (int j = 0; j < 8; j++) jskip[j] = (s0 + 8*j > lim);

            // ---- scores ----
            float sc[8][4];
#pragma unroll
            for (int j = 0; j < 8; j++) { sc[j][0]=sc[j][1]=sc[j][2]=sc[j][3]=0.f; }
#pragma unroll
            for (int kk = 0; kk < 4; kk++) {
#pragma unroll
                for (int np = 0; np < 4; np++) {
                    if (jskip[2*np]) continue;
                    uint32_t th[4], tl[4];
                    ldsm4(th, aKh + np*(16*ARS) + kk*32);
                    ldsm4(tl, aKl + np*(16*ARS) + kk*32);
                    mma16816(sc[2*np],   qh[kk], th);
                    mma16816(sc[2*np+1], qh[kk], th+2);
                    mma16816(sc[2*np],   ql[kk], th);
                    mma16816(sc[2*np+1], ql[kk], th+2);
                    mma16816(sc[2*np],   qh[kk], tl);
                    mma16816(sc[2*np+1], qh[kk], tl+2);
                }
            }

            // ---- bias gather + causal mask ----
#pragma unroll
            for (int j = 0; j < 8; j++) {
                if (jskip[j]) continue;
                int coll = 8*j + (lane & 3)*2;
#pragma unroll
                for (int hh = 0; hh < 2; hh++) {
                    int qr = 16*w + qrow0 + 8*hh;
                    int2 bk = *(const int2*)(bbase + (size_t)(t0 + qr) * bstr + s0 + coll);
                    bool v0 = (s0 + coll)     <= (t0 + qr);
                    bool v1 = (s0 + coll + 1) <= (t0 + qr);
                    sc[j][2*hh]   = v0 ? (sc[j][2*hh]   + sVals[qr*32 + bk.x]) : -1e30f;
                    sc[j][2*hh+1] = v1 ? (sc[j][2*hh+1] + sVals[qr*32 + bk.y]) : -1e30f;
                }
            }

            // ---- online softmax (base-2) ----
#pragma unroll
            for (int hh = 0; hh < 2; hh++) {
                float rm = -1e30f;
#pragma unroll
                for (int j = 0; j < 8; j++)
                    if (!jskip[j]) rm = fmaxf(rm, fmaxf(sc[j][2*hh], sc[j][2*hh+1]));
                rm = fmaxf(rm, __shfl_xor_sync(0xffffffffu, rm, 1));
                rm = fmaxf(rm, __shfl_xor_sync(0xffffffffu, rm, 2));
                float mnew = fmaxf(m_[hh], rm);
                float scale = ex2(m_[hh] - mnew);
                float sum = 0.f;
#pragma unroll
                for (int j = 0; j < 8; j++) {
                    if (jskip[j]) { sc[j][2*hh] = 0.f; sc[j][2*hh+1] = 0.f; continue; }
                    float p0 = ex2(sc[j][2*hh]   - mnew);
                    float p1 = ex2(sc[j][2*hh+1] - mnew);
                    sc[j][2*hh] = p0; sc[j][2*hh+1] = p1;
                    sum += p0 + p1;
                }
                sum += __shfl_xor_sync(0xffffffffu, sum, 1);
                sum += __shfl_xor_sync(0xffffffffu, sum, 2);
                l_[hh] = l_[hh] * scale + sum;
                m_[hh] = mnew;
#pragma unroll
                for (int j = 0; j < 8; j++) {
                    o[j][2*hh]   *= scale;
                    o[j][2*hh+1] *= scale;
                }
            }

            // ---- O += P V ----
#pragma unroll
            for (int kk2 = 0; kk2 < 4; kk2++) {
                if (jskip[2*kk2]) continue;
                uint32_t ahi[4], alo[4];
                split2(sc[2*kk2][0],   sc[2*kk2][1],   ahi[0], alo[0]);
                split2(sc[2*kk2][2],   sc[2*kk2][3],   ahi[1], alo[1]);
                split2(sc[2*kk2+1][0], sc[2*kk2+1][1], ahi[2], alo[2]);
                split2(sc[2*kk2+1][2], sc[2*kk2+1][3], ahi[3], alo[3]);
#pragma unroll
                for (int ng = 0; ng < 4; ng++) {
                    uint32_t vh4[4], vl4[4];
                    ldsm4t(vh4, aVh + kk2*(16*ARS) + ng*32);
                    ldsm4t(vl4, aVl + kk2*(16*ARS) + ng*32);
                    mma16816(o[2*ng],   ahi, vh4);
                    mma16816(o[2*ng+1], ahi, vh4+2);
                    mma16816(o[2*ng],   alo, vh4);
                    mma16816(o[2*ng+1], alo, vh4+2);
                    mma16816(o[2*ng],   ahi, vl4);
                    mma16816(o[2*ng+1], ahi, vl4+2);
                }
            }
        }
    }

    // ---- ngram diagonal key: SIMT scalar merge ----
    if (var != 0) {
#pragma unroll
        for (int hh = 0; hh < 2; hh++) {
            int qr = 16*w + qrow0 + 8*hh;
            int t = t0 + qr;
            size_t rowoff = ((size_t)bh * TGTn + qoff + t) * HDn;
            size_t doff = rowoff + (lane & 3) * 16;
            float dot = 0.f;
#pragma unroll
            for (int u = 0; u < 2; u++) {
                uint4 qh4 = *(const uint4*)(g_q_h + doff + u*8);
                uint4 ql4 = *(const uint4*)(g_q_l + doff + u*8);
                uint4 kh4 = *(const uint4*)(g_k_h + doff + u*8);
                uint4 kl4 = *(const uint4*)(g_k_l + doff + u*8);
                const uint32_t* qh_ = &qh4.x; const uint32_t* ql_ = &ql4.x;
                const uint32_t* kh_ = &kh4.x; const uint32_t* kl_ = &kl4.x;
#pragma unroll
                for (int c = 0; c < 4; c++) {
                    float2 qv = h2sum(qh_[c], ql_[c]);
                    float2 kv = h2sum(kh_[c], kl_[c]);
                    dot += qv.x*kv.x + qv.y*kv.y;
                }
            }
            dot += __shfl_xor_sync(0xffffffffu, dot, 1);
            dot += __shfl_xor_sync(0xffffffffu, dot, 2);
            int bkt = bbase[(size_t)t * bstr + Tn + t];
            float sd = dot + sVals[qr*32 + bkt];

            float mnew = fmaxf(m_[hh], sd);
            float scale = ex2(m_[hh] - mnew);
            float pd = ex2(sd - mnew);
            l_[hh] = l_[hh] * scale + pd;
            m_[hh] = mnew;
#pragma unroll
            for (int j = 0; j < 8; j++) {
                int col = 8*j + (lane & 3)*2;
                uint32_t vh = *(const uint32_t*)(g_v_h + rowoff + col);
                uint32_t vl = *(const uint32_t*)(g_v_l + rowoff + col);
                float2 vv = h2sum(vh, vl);
                o[j][2*hh]   = o[j][2*hh]   * scale + pd * vv.x;
                o[j][2*hh+1] = o[j][2*hh+1] * scale + pd * vv.y;
            }
        }
    }

    // ---- epilogue: ctx (fp16 hi/lo) = O / l ----
#pragma unroll
    for (int hh = 0; hh < 2; hh++) {
        int qr = 16*w + qrow0 + 8*hh;
        int tg = qoff + t0 + qr;
        float inv = 1.0f / l_[hh];
#pragma unroll
        for (int j = 0; j < 8; j++) {
            int col = 8*j + (lane & 3)*2;
            float x0 = o[j][2*hh] * inv, x1 = o[j][2*hh+1] * inv;
            uint32_t hi, lo;
            split2(x0, x1, hi, lo);
            size_t off = ((size_t)tg * Bn + b) * En + h * HDn + col;
            *(uint32_t*)(g_ctx_h + off) = hi;
            *(uint32_t*)(g_ctx_l + off) = lo;
        }
    }
}

// ---------------------------------------------------------------------------
extern "C" void kernel_launch(void* const* d_in, const int* in_sizes, int n_in,
                              void* d_out, int out_size) {
    const float* query = (const float*)d_in[0];
    const float* ipw   = (const float*)d_in[1];
    const float* ipb   = (const float*)d_in[2];
    const float* relw  = (const float*)d_in[3];
    const float* relb  = (const float*)d_in[4];
    const float* outw  = (const float*)d_in[5];
    const float* outb  = (const float*)d_in[6];
    const int*   mb    = (const int*)d_in[7];
    const int*   pb    = (const int*)d_in[8];
    float* out = (float*)d_out;

    cudaFuncSetAttribute((const void*)hgemm2<0>,
                         cudaFuncAttributeMaxDynamicSharedMemorySize, SM_GEMM);
    cudaFuncSetAttribute((const void*)hgemm2<1>,
                         cudaFuncAttributeMaxDynamicSharedMemorySize, SM_GEMM);
    cudaFuncSetAttribute((const void*)attn3,
                         cudaFuncAttributeMaxDynamicSharedMemorySize, SM_ATTN);

    // 0) fused pre-convert
    convert_all<<<10752, 256>>>(query, ipw, relw, outw);
    // 1) qkv + rel-vals projection (merged, N = 3072 + 512)
    hgemm2<1><<<dim3(28, 48), 256, SM_GEMM>>>(ipb, relb, nullptr, Mrows, 3*En + NBn*Hn, En);
    // 2) fused HMMA flash attention
    attn3<<<dim3(4, 64, 3), 256, SM_ATTN>>>(mb, pb);
    // 3) output projection -> d_out (BM=128 restored)
    hgemm2<0><<<dim3(8, 48), 256, SM_GEMM>>>(outb, nullptr, out, Mrows, En, En);
}